// round 1
// baseline (speedup 1.0000x reference)
#include <cuda_runtime.h>
#include <stdint.h>

// Problem constants
#define VS 64
#define DEPTH_HW 256
#define IMG_H 1024
#define IMG_W 1280
#define BATCH 8
#define OUT_PER_B (VS * VS * VS)           // 262144
#define N_OUT (BATCH * OUT_PER_B)          // 2097152
#define N_PIX (1024 * 1024)                // non-padded pixels per batch

// Zero-init the output (poisoned to 0xAA by harness). float4 stores.
__global__ void vox_zero_kernel(float4* __restrict__ out) {
    int i = blockIdx.x * blockDim.x + threadIdx.x;   // 0 .. N_OUT/4-1
    out[i] = make_float4(0.f, 0.f, 0.f, 0.f);
}

// One thread per non-padded pixel; loop over the 8 batches with the ray in regs.
__global__ void __launch_bounds__(256)
vox_scatter_kernel(const float* __restrict__ depth,   // [8,256,256]
                   const float* __restrict__ ray,     // [1280*1024, 3]
                   float* __restrict__ out)           // [8,64,64,64]
{
    const int n = blockIdx.x * blockDim.x + threadIdx.x;   // 0 .. N_PIX-1
    const int y  = n & 1023;          // height coord
    const int xr = n >> 10;           // width coord inside non-padded region, 0..1023

    // ray index follows column-major flatten: idx = x*1024 + y, x = xr+128
    const int ridx = ((xr + 128) << 10) + y;
    const float rx = __ldg(&ray[3 * ridx + 0]);
    const float ry = __ldg(&ray[3 * ridx + 1]);
    const float rz = __ldg(&ray[3 * ridx + 2]);

    const float scale = 64.0f / 3.0f;     // matches f32(64/3) in reference
    const int doff = ((y >> 2) << 8) + (xr >> 2);   // depth[b, y/4, xr/4]

#pragma unroll
    for (int b = 0; b < BATCH; b++) {
        const float d = __ldg(&depth[b * (DEPTH_HW * DEPTH_HW) + doff]);

        // Exactly replicate reference f32 op sequence: mul, add, mul, round-half-even.
        // __fmul_rn/__fadd_rn prevent FFMA contraction (which would perturb
        // points near .5 rounding boundaries).
        const float px = __fmul_rn(rx, d);
        const float py = __fmul_rn(ry, d);
        const float pz = __fmul_rn(rz, d);

        const int ix = __float2int_rn(__fmul_rn(__fadd_rn(px, 1.5f), scale));
        const int iy = __float2int_rn(__fmul_rn(__fadd_rn(py, 1.5f), scale));
        const int iz = __float2int_rn(__fmul_rn(pz, scale));

        if (((unsigned)ix < 64u) & ((unsigned)iy < 64u) & ((unsigned)iz < 64u)) {
            const int lin = ((ix << 6) + iy) * 64 + iz;
            out[b * OUT_PER_B + lin] = 1.0f;     // all writers write 1.0 -> race-free
        }
    }

    // Padded columns (depth==0) always map to voxel (32,32,0) for every batch.
    if (n < BATCH) {
        out[n * OUT_PER_B + ((32 * 64 + 32) * 64 + 0)] = 1.0f;
    }
}

extern "C" void kernel_launch(void* const* d_in, const int* in_sizes, int n_in,
                              void* d_out, int out_size)
{
    const float* depth = (const float*)d_in[0];
    const float* ray   = (const float*)d_in[1];
    // Defensive: identify by element count (depth = 524288, ray = 3932160)
    if (n_in >= 2 && in_sizes[0] == IMG_W * IMG_H * 3) {
        ray   = (const float*)d_in[0];
        depth = (const float*)d_in[1];
    }
    float* out = (float*)d_out;

    vox_zero_kernel<<<N_OUT / 4 / 256, 256>>>((float4*)out);
    vox_scatter_kernel<<<N_PIX / 256, 256>>>(depth, ray, out);
}

// round 2
// speedup vs baseline: 1.2668x; 1.2668x over previous
#include <cuda_runtime.h>
#include <stdint.h>

// Problem constants
#define VS 64
#define DEPTH_HW 256
#define IMG_H 1024
#define IMG_W 1280
#define BATCH 8
#define OUT_PER_B (VS * VS * VS)           // 262144 voxels per batch
#define N_OUT (BATCH * OUT_PER_B)          // 2097152 floats out
#define NBW (OUT_PER_B / 32)               // 8192 bit-words per batch

// 256KB occupancy bit-grid. Zero-initialized at module load; the expand
// kernel restores it to zero every call, so every kernel_launch (correctness
// run + each graph replay) starts from a clean grid.
__device__ unsigned g_bits[BATCH * NBW];

// Scatter: one thread per non-padded pixel. Warp covers a 4(y) x 8(x) pixel
// tile so the per-batch depth load is a single 128B line (1 wavefront).
// In-range points set one bit via atomicOr (compiles to REDG.OR -> resolved
// at the L2 atomic ALU, off the L1tex wavefront path).
__global__ void __launch_bounds__(256)
vox_scatter_kernel(const float* __restrict__ depth,   // [8,256,256]
                   const float* __restrict__ ray)     // [1280*1024, 3]
{
    const int lane = threadIdx.x & 31;
    const int wid  = threadIdx.x >> 5;            // 0..7
    const int bx   = blockIdx.x & 127;            // 128 x-tiles of width 8
    const int by   = blockIdx.x >> 7;             // 32  y-tiles of height 32

    const int y  = by * 32 + wid * 4 + (lane & 3);   // 0..1023
    const int xr = bx * 8 + (lane >> 2);             // 0..1023 (non-padded x)

    // ray index: column-major flatten idx = x*1024 + y, x = xr + 128
    const int ridx = ((xr + 128) << 10) + y;
    const float rx = __ldg(&ray[3 * ridx + 0]);
    const float ry = __ldg(&ray[3 * ridx + 1]);
    const float rz = __ldg(&ray[3 * ridx + 2]);

    const float scale = 64.0f / 3.0f;
    const int doff = ((y >> 2) << 8) + (xr >> 2);    // depth[b, y/4, xr/4]

#pragma unroll
    for (int b = 0; b < BATCH; b++) {
        const float d = __ldg(&depth[b * (DEPTH_HW * DEPTH_HW) + doff]);

        // Replicate reference f32 op sequence exactly: mul, add, mul,
        // round-half-even. _rn intrinsics forbid FFMA contraction.
        const float px = __fmul_rn(rx, d);
        const float py = __fmul_rn(ry, d);
        const float pz = __fmul_rn(rz, d);

        const int ix = __float2int_rn(__fmul_rn(__fadd_rn(px, 1.5f), scale));
        const int iy = __float2int_rn(__fmul_rn(__fadd_rn(py, 1.5f), scale));
        const int iz = __float2int_rn(__fmul_rn(pz, scale));

        if (((unsigned)ix < 64u) & ((unsigned)iy < 64u) & ((unsigned)iz < 64u)) {
            const int lin = ((ix << 6) + iy) * 64 + iz;
            atomicOr(&g_bits[b * NBW + (lin >> 5)], 1u << (lin & 31));
        }
    }

    // Padded columns all have depth==0 -> voxel (32,32,0), lin = 133120
    // = word 4160, bit 0, for every batch.
    if (blockIdx.x == 0 && threadIdx.x < BATCH) {
        atomicOr(&g_bits[threadIdx.x * NBW + 4160], 1u);
    }
}

// Expand: bit-grid -> full float output (writes every element, so no
// separate zero pass is needed). 8 consecutive threads share one bit-word;
// each converts 4 bits into one coalesced float4 store. The lane owning
// bit 0 of the word resets it to zero afterward (warp-converged: the load
// instruction completes for all lanes before the store issues; words never
// span warps).
__global__ void __launch_bounds__(256)
vox_expand_kernel(float4* __restrict__ out)
{
    const int tid = blockIdx.x * 256 + threadIdx.x;   // 0 .. N_OUT/4 - 1
    const int w   = tid >> 3;
    const unsigned v  = g_bits[w];
    const unsigned sh = (tid & 7) * 4;

    float4 o;
    o.x = ((v >> (sh + 0)) & 1u) ? 1.0f : 0.0f;
    o.y = ((v >> (sh + 1)) & 1u) ? 1.0f : 0.0f;
    o.z = ((v >> (sh + 2)) & 1u) ? 1.0f : 0.0f;
    o.w = ((v >> (sh + 3)) & 1u) ? 1.0f : 0.0f;
    out[tid] = o;

    if ((tid & 7) == 0) g_bits[w] = 0u;
}

extern "C" void kernel_launch(void* const* d_in, const int* in_sizes, int n_in,
                              void* d_out, int out_size)
{
    const float* depth = (const float*)d_in[0];
    const float* ray   = (const float*)d_in[1];
    // Defensive: identify by element count (depth = 524288, ray = 3932160)
    if (n_in >= 2 && in_sizes[0] == IMG_W * IMG_H * 3) {
        ray   = (const float*)d_in[0];
        depth = (const float*)d_in[1];
    }
    float* out = (float*)d_out;

    vox_scatter_kernel<<<4096, 256>>>(depth, ray);
    vox_expand_kernel<<<(N_OUT / 4) / 256, 256>>>((float4*)out);
}

// round 3
// speedup vs baseline: 2.1632x; 1.7076x over previous
#include <cuda_runtime.h>
#include <stdint.h>

// Problem constants
#define VS 64
#define DEPTH_HW 256
#define IMG_H 1024
#define IMG_W 1280
#define BATCH 8
#define OUT_PER_B (VS * VS * VS)           // 262144 voxels per batch
#define N_OUT (BATCH * OUT_PER_B)          // 2097152 floats out
#define NBW (OUT_PER_B / 32)               // 8192 bit-words per batch
#define NW  (BATCH * NBW)                  // 65536 words per replica
#define R   16                             // replicas (breaks hot-address atomic serialization)

// R replicated occupancy bit-grids (4MB). Zero at module load; the expand
// kernel restores them to zero every call, so each kernel_launch (correctness
// run + every graph replay) starts clean.
__device__ unsigned g_bits[R][NW];

// Scatter: one thread per non-padded pixel. Warp covers a 4(y) x 8(x) tile so
// the per-batch depth load is a single 128B line. Each warp ORs bits into its
// own replica, spreading the hot-center atomic traffic over 16 distinct
// addresses/LTS partitions instead of serializing on one.
__global__ void __launch_bounds__(256)
vox_scatter_kernel(const float* __restrict__ depth,   // [8,256,256]
                   const float* __restrict__ ray)     // [1280*1024, 3]
{
    const int lane = threadIdx.x & 31;
    const int wid  = threadIdx.x >> 5;            // 0..7
    const int bx   = blockIdx.x & 127;            // 128 x-tiles of width 8
    const int by   = blockIdx.x >> 7;             // 32  y-tiles of height 32

    const int y  = by * 32 + wid * 4 + (lane & 3);   // 0..1023
    const int xr = bx * 8 + (lane >> 2);             // 0..1023 (non-padded x)

    unsigned* __restrict__ bits = g_bits[((blockIdx.x << 3) + wid) & (R - 1)];

    // ray index: column-major flatten idx = x*1024 + y, x = xr + 128
    const int ridx = ((xr + 128) << 10) + y;
    const float rx = __ldg(&ray[3 * ridx + 0]);
    const float ry = __ldg(&ray[3 * ridx + 1]);
    const float rz = __ldg(&ray[3 * ridx + 2]);

    const float scale = 64.0f / 3.0f;
    const int doff = ((y >> 2) << 8) + (xr >> 2);    // depth[b, y/4, xr/4]

#pragma unroll
    for (int b = 0; b < BATCH; b++) {
        const float d = __ldg(&depth[b * (DEPTH_HW * DEPTH_HW) + doff]);

        // Replicate reference f32 op sequence exactly: mul, add, mul,
        // round-half-even. _rn intrinsics forbid FFMA contraction.
        const float px = __fmul_rn(rx, d);
        const float py = __fmul_rn(ry, d);
        const float pz = __fmul_rn(rz, d);

        const int ix = __float2int_rn(__fmul_rn(__fadd_rn(px, 1.5f), scale));
        const int iy = __float2int_rn(__fmul_rn(__fadd_rn(py, 1.5f), scale));
        const int iz = __float2int_rn(__fmul_rn(pz, scale));

        if (((unsigned)ix < 64u) & ((unsigned)iy < 64u) & ((unsigned)iz < 64u)) {
            const int lin = ((ix << 6) + iy) * 64 + iz;
            atomicOr(&bits[b * NBW + (lin >> 5)], 1u << (lin & 31));
        }
    }

    // Padded columns all have depth==0 -> voxel (32,32,0), lin = 133120
    // = word 4160, bit 0, for every batch. Write into replica 0.
    if (blockIdx.x == 0 && threadIdx.x < BATCH) {
        atomicOr(&g_bits[0][threadIdx.x * NBW + 4160], 1u);
    }
}

// Expand: OR the R replica words, emit floats (writes every output element, so
// no separate zero pass), and reset the replicas to zero. 8 consecutive
// threads (one warp-subgroup; words never span warps since 8 | 32) share one
// bit-word; each converts 4 bits into one coalesced float4 store. The lane
// owning bit 0 resets all replicas afterward (in-warp program order: every
// load instruction issues before the zeroing stores).
__global__ void __launch_bounds__(256)
vox_expand_kernel(float4* __restrict__ out)
{
    const int tid = blockIdx.x * 256 + threadIdx.x;   // 0 .. N_OUT/4 - 1
    const int w   = tid >> 3;

    unsigned v = 0;
#pragma unroll
    for (int r = 0; r < R; r++) v |= g_bits[r][w];

    const unsigned sh = (tid & 7) * 4;
    float4 o;
    o.x = ((v >> (sh + 0)) & 1u) ? 1.0f : 0.0f;
    o.y = ((v >> (sh + 1)) & 1u) ? 1.0f : 0.0f;
    o.z = ((v >> (sh + 2)) & 1u) ? 1.0f : 0.0f;
    o.w = ((v >> (sh + 3)) & 1u) ? 1.0f : 0.0f;
    out[tid] = o;

    if ((tid & 7) == 0) {
#pragma unroll
        for (int r = 0; r < R; r++) g_bits[r][w] = 0u;
    }
}

extern "C" void kernel_launch(void* const* d_in, const int* in_sizes, int n_in,
                              void* d_out, int out_size)
{
    const float* depth = (const float*)d_in[0];
    const float* ray   = (const float*)d_in[1];
    // Defensive: identify by element count (depth = 524288, ray = 3932160)
    if (n_in >= 2 && in_sizes[0] == IMG_W * IMG_H * 3) {
        ray   = (const float*)d_in[0];
        depth = (const float*)d_in[1];
    }
    float* out = (float*)d_out;

    vox_scatter_kernel<<<4096, 256>>>(depth, ray);
    vox_expand_kernel<<<(N_OUT / 4) / 256, 256>>>((float4*)out);
}